// round 14
// baseline (speedup 1.0000x reference)
#include <cuda_runtime.h>
#include <cuda_fp16.h>
#include <cstdint>

// ---------------------------------------------------------------------------
// B=8192, D=256.
// loss = -sum_ij log_sigmoid(y_ij * (che_i . loc_j * exp(t') + b)) / B
// y = +1 diag, -1 off-diag.
//
// R14: R13 (fp16-accum MMA, 256x128 tiles, ring-2, 2 CTAs/SM) +
//      packed f16x2 off-diagonal epilogue: hfma2 for z, ex2.approx.f16x2
//      for e (halves MUFU + trims issue slots); S1/S2 still accumulated
//      in f32. Diagonal tiles keep the exact f32 path.
// ---------------------------------------------------------------------------

#define BATCH  8192
#define DIM    256
#define TM     256
#define TN     128
#define NTILES ((BATCH / TM) * (BATCH / TN))   // 2048
#define NWARPS 8

#define CHUNK_BYTES (384 * 128)                // (256 A + 128 B) rows x 128B
#define SMEM_TOTAL  (2 * CHUNK_BYTES)          // 98304

// Scratch (device globals; no allocation allowed): fp16 matrices
__device__ __half g_che[BATCH * DIM];
__device__ __half g_loc[BATCH * DIM];
__device__ float g_acc;
__device__ unsigned g_tile_ctr;
__device__ unsigned g_bar;      // monotonic barrier counter (epoch trick)
__device__ unsigned g_done;     // monotonic completion counter

__device__ __forceinline__ uint32_t smem_u32(const void* p) {
    uint32_t a;
    asm("{ .reg .u64 t; cvta.to.shared.u64 t, %1; cvt.u32.u64 %0, t; }"
        : "=r"(a) : "l"(p));
    return a;
}

__device__ __forceinline__ void ldmatrix_x4(uint32_t* r, uint32_t addr) {
    asm volatile("ldmatrix.sync.aligned.m8n8.x4.shared.b16 {%0,%1,%2,%3}, [%4];"
                 : "=r"(r[0]), "=r"(r[1]), "=r"(r[2]), "=r"(r[3])
                 : "r"(addr));
}

// fp16-accumulator MMA: D(16x8,f16) += A(16x16,f16) x B(16x8,f16)
__device__ __forceinline__ void mma_f16acc(uint32_t* c, const uint32_t* a,
                                           uint32_t b0, uint32_t b1) {
    asm volatile(
        "mma.sync.aligned.m16n8k16.row.col.f16.f16.f16.f16 "
        "{%0,%1}, {%2,%3,%4,%5}, {%6,%7}, {%0,%1};"
        : "+r"(c[0]), "+r"(c[1])
        : "r"(a[0]), "r"(a[1]), "r"(a[2]), "r"(a[3]), "r"(b0), "r"(b1));
}

#define CP_ASYNC16(dst, src) \
    asm volatile("cp.async.cg.shared.global [%0], [%1], 16;" \
                 :: "r"(dst), "l"(src) : "memory")
#define CP_COMMIT() asm volatile("cp.async.commit_group;" ::: "memory")
#define CP_WAIT(n)  asm volatile("cp.async.wait_group %0;" :: "n"(n) : "memory")

// ---------------------------------------------------------------------------
// Prefetch one K=64 chunk (256 A rows + 128 B rows, 128B each) into a
// swizzled ring slot. 256 threads x 12 cp.async of 16B.
// ---------------------------------------------------------------------------
__device__ __forceinline__ void prefetch_chunk(uint32_t dstBase, int m0, int n0,
                                               int chunk, int tid)
{
    int r0 = tid >> 3;                       // 0..31
    int cc = tid & 7;                        // 16B slot in 128B row
    uint32_t swx = ((uint32_t)(cc << 4)) ^ ((uint32_t)((r0 & 7) << 4));
    const __half* srcA = g_che + (size_t)(m0 + r0) * DIM + chunk * 64 + cc * 8;
    const __half* srcB = g_loc + (size_t)(n0 + r0) * DIM + chunk * 64 + cc * 8;
    #pragma unroll
    for (int it = 0; it < 8; it++) {
        uint32_t dst = dstBase + (uint32_t)((r0 + it * 32) << 7) + swx;
        CP_ASYNC16(dst, srcA + (size_t)(it * 32) * DIM);
    }
    #pragma unroll
    for (int it = 0; it < 4; it++) {
        uint32_t dst = dstBase + (uint32_t)((r0 + it * 32 + TM) << 7) + swx;
        CP_ASYNC16(dst, srcB + (size_t)(it * 32) * DIM);
    }
}

// ---------------------------------------------------------------------------
// Compute one K=64 chunk: 4 k16 steps over this warp's 64x64 fragment.
// ---------------------------------------------------------------------------
__device__ __forceinline__ void compute_chunk(uint32_t base,
                                              const uint32_t* aRB, const uint32_t* aX,
                                              const uint32_t* bRB, const uint32_t* bX,
                                              uint32_t kloA, uint32_t kloB,
                                              uint32_t (*c)[2])
{
    #pragma unroll
    for (int ks = 0; ks < 4; ks++) {
        uint32_t koff = (uint32_t)(ks << 5);   // 32B per k16 step
        uint32_t a[4][4], b[4][4];
        #pragma unroll
        for (int i = 0; i < 4; i++)
            ldmatrix_x4(a[i], base + aRB[i] + ((koff + kloA) ^ aX[i]));
        #pragma unroll
        for (int q = 0; q < 4; q++)
            ldmatrix_x4(b[q], base + bRB[q] + ((koff + kloB) ^ bX[q]));
        #pragma unroll
        for (int mt = 0; mt < 4; mt++) {
            #pragma unroll
            for (int nt = 0; nt < 8; nt++) {
                uint32_t b0 = b[nt >> 1][(nt & 1) ? 2 : 0];
                uint32_t b1 = b[nt >> 1][(nt & 1) ? 3 : 1];
                mma_f16acc(c[mt * 8 + nt], a[mt], b0, b1);
            }
        }
    }
}

// ---------------------------------------------------------------------------
// Fused kernel: norm -> device barrier -> persistent GEMM+loss -> output.
// ---------------------------------------------------------------------------
__global__ __launch_bounds__(256, 2)
void fused_loss_kernel(const float* __restrict__ loc,
                       const float* __restrict__ che,
                       const float* __restrict__ t_prime,
                       const float* __restrict__ b_in,
                       float* __restrict__ out)
{
    extern __shared__ __align__(128) char smem[];
    const uint32_t sBase = smem_u32(smem);
    const unsigned NC = gridDim.x;

    __shared__ unsigned sh_next;
    __shared__ float shred[NWARPS];

    int tid = threadIdx.x;
    int wid = tid >> 5;
    int lane = tid & 31;

    // ================= Phase 1: row L2-normalize -> fp16 ====================
    {
        int gwarp = blockIdx.x * NWARPS + wid;
        for (int row = gwarp; row < BATCH; row += (int)NC * NWARPS) {
            const float4* l4 = reinterpret_cast<const float4*>(loc + row * DIM) + lane * 2;
            const float4* c4 = reinterpret_cast<const float4*>(che + row * DIM) + lane * 2;
            float4 a0 = l4[0], a1 = l4[1];
            float4 b0 = c4[0], b1 = c4[1];

            float s0 = a0.x*a0.x + a0.y*a0.y + a0.z*a0.z + a0.w*a0.w
                     + a1.x*a1.x + a1.y*a1.y + a1.z*a1.z + a1.w*a1.w;
            float s1 = b0.x*b0.x + b0.y*b0.y + b0.z*b0.z + b0.w*b0.w
                     + b1.x*b1.x + b1.y*b1.y + b1.z*b1.z + b1.w*b1.w;
            #pragma unroll
            for (int o = 16; o > 0; o >>= 1) {
                s0 += __shfl_xor_sync(0xFFFFFFFFu, s0, o);
                s1 += __shfl_xor_sync(0xFFFFFFFFu, s1, o);
            }
            float r0 = rsqrtf(s0);
            float r1 = rsqrtf(s1);

            __half2 h[4];
            h[0] = __float22half2_rn(make_float2(a0.x*r0, a0.y*r0));
            h[1] = __float22half2_rn(make_float2(a0.z*r0, a0.w*r0));
            h[2] = __float22half2_rn(make_float2(a1.x*r0, a1.y*r0));
            h[3] = __float22half2_rn(make_float2(a1.z*r0, a1.w*r0));
            *reinterpret_cast<uint4*>(g_loc + row * DIM + lane * 8) =
                *reinterpret_cast<uint4*>(h);

            h[0] = __float22half2_rn(make_float2(b0.x*r1, b0.y*r1));
            h[1] = __float22half2_rn(make_float2(b0.z*r1, b0.w*r1));
            h[2] = __float22half2_rn(make_float2(b1.x*r1, b1.y*r1));
            h[3] = __float22half2_rn(make_float2(b1.z*r1, b1.w*r1));
            *reinterpret_cast<uint4*>(g_che + row * DIM + lane * 8) =
                *reinterpret_cast<uint4*>(h);
        }
    }

    float scale = expf(t_prime[0]);
    float shift = b_in[0];

    if (blockIdx.x == 0 && tid == 0) {
        atomicExch(&g_tile_ctr, 0u);
        atomicExch(&g_acc, 0.0f);
    }
    __threadfence();
    __syncthreads();

    // ============ device-wide epoch spin barrier (all CTAs resident) =======
    if (tid == 0) {
        unsigned t = atomicAdd(&g_bar, 1u);
        unsigned target = (t / NC + 1u) * NC;
        while (atomicAdd(&g_bar, 0u) < target) { }
    }
    __threadfence();
    __syncthreads();

    // ================= Phase 2: persistent GEMM + loss ======================
    int am = (wid & 3) * 64;
    int bn = (wid >> 2) * 64;

    uint32_t aRB[4], aX[4], bRB[4], bX[4];
    #pragma unroll
    for (int i = 0; i < 4; i++) {
        int r = am + i * 16 + (lane & 15);
        aRB[i] = (uint32_t)(r << 7);
        aX[i]  = (uint32_t)((r & 7) << 4);
    }
    #pragma unroll
    for (int q = 0; q < 4; q++) {
        int r = TM + bn + q * 16 + ((lane >> 4) << 3) + (lane & 7);
        bRB[q] = (uint32_t)(r << 7);
        bX[q]  = (uint32_t)((r & 7) << 4);
    }
    uint32_t kloA = (uint32_t)((lane >> 4) << 4);
    uint32_t kloB = (uint32_t)(((lane >> 3) & 1) << 4);

    uint32_t c[32][2];
    #pragma unroll
    for (int i = 0; i < 32; i++) { c[i][0] = 0u; c[i][1] = 0u; }

    float acc = 0.0f;                 // exact diagonal-tile contributions
    float S1a = 0.f, S1b = 0.f;       // running sum(e)    (off-diag tiles)
    float S2a = 0.f, S2b = 0.f;       // running sum(e^2)
    const float LOG2E = 1.4426950408889634f;
    float k1 = scale * LOG2E;
    float k0 = shift * LOG2E;
    __half2 K1h = __float2half2_rn(k1);
    __half2 K0h = __float2half2_rn(k0);

    if (tid == 0) sh_next = atomicAdd(&g_tile_ctr, 1u);
    __syncthreads();
    unsigned cur = sh_next;

    int m0 = (int)(cur & 31) * TM;
    int n0 = (int)(cur >> 5) * TN;

    // warm: chunk 0 of first tile into slot 0
    prefetch_chunk(sBase, m0, n0, 0, tid);
    CP_COMMIT();

    int sc = 0;                       // ring slot of the chunk being computed
    unsigned nxt = 0;
    for (;;) {
        int nm0 = 0, nn0 = 0;

        #pragma unroll
        for (int k = 0; k < 4; k++) {
            __syncthreads();       // all warps done with slot sc^1's old data

            if (k == 0) {
                if (tid == 0) sh_next = atomicAdd(&g_tile_ctr, 1u);
            } else if (k == 1) {
                nxt = sh_next;                // written k=0, barrier at k=1
                nm0 = (int)(nxt & 31) * TM;
                nn0 = (int)(nxt >> 5) * TN;
            }

            // prefetch the NEXT stream chunk into the other slot
            uint32_t pslot = sBase + (uint32_t)((sc ^ 1) * CHUNK_BYTES);
            if (k < 3)             prefetch_chunk(pslot, m0, n0, k + 1, tid);
            else if (nxt < NTILES) prefetch_chunk(pslot, nm0, nn0, 0, tid);
            CP_COMMIT();

            CP_WAIT(1);            // current chunk's group complete
            compute_chunk(sBase + (uint32_t)(sc * CHUNK_BYTES),
                          aRB, aX, bRB, bX, kloA, kloB, c);
            sc ^= 1;
        }

        // ---- epilogue for tile cur (next tile's chunk-0 load streams) ----
        bool diag = (n0 == m0) || (n0 == m0 + TN);
        if (!diag) {
            // packed f16x2: z = hfma2(d, K1, K0); e = 2^z; S1 += e, S2 += e^2
            #pragma unroll
            for (int i = 0; i < 32; i++) {
                __half2 z0 = __hfma2(*reinterpret_cast<__half2*>(&c[i][0]), K1h, K0h);
                __half2 z1 = __hfma2(*reinterpret_cast<__half2*>(&c[i][1]), K1h, K0h);
                float2 f0 = __half22float2(h2exp2(z0));
                float2 f1 = __half22float2(h2exp2(z1));
                S1a += f0.x; S2a = fmaf(f0.x, f0.x, S2a);
                S1b += f0.y; S2b = fmaf(f0.y, f0.y, S2b);
                S1a += f1.x; S2a = fmaf(f1.x, f1.x, S2a);
                S1b += f1.y; S2b = fmaf(f1.y, f1.y, S2b);
                c[i][0] = 0u; c[i][1] = 0u;
            }
        } else {
            // tile contains diagonal elements: exact per-element handling
            int rbase = m0 + am + (lane >> 2);
            int cbase = n0 + bn + (lane & 3) * 2;
            #pragma unroll
            for (int mt = 0; mt < 4; mt++) {
                #pragma unroll
                for (int nt = 0; nt < 8; nt++) {
                    uint32_t* cc = c[mt * 8 + nt];
                    int col0 = cbase + nt * 8;
                    #pragma unroll
                    for (int j = 0; j < 2; j++) {
                        float2 f = __half22float2(*reinterpret_cast<__half2*>(&cc[j]));
                        int row = rbase + mt * 16 + j * 8;
                        #pragma unroll
                        for (int u = 0; u < 2; u++) {
                            float d = (u == 0) ? f.x : f.y;
                            int col = col0 + u;
                            float z = fmaf(d, scale, shift);
                            float v = (row == col) ? z : -z;   // y*z
                            float av = fabsf(v);
                            float e = __expf(-av);
                            float l;
                            if (e < 0.0625f) {
                                l = e * fmaf(e, fmaf(e, 0.33333333f, -0.5f), 1.0f);
                            } else {
                                l = log1pf(e);                 // near-diagonal only
                            }
                            acc += fmaxf(-v, 0.0f) + l;        // softplus(-v)
                        }
                        cc[j] = 0u;
                    }
                }
            }
        }

        if (nxt >= NTILES) break;
        cur = nxt; m0 = nm0; n0 = nn0;
    }

    // fold running sums: sum log1p(e) ~ S1 - S2/2
    acc += (S1a + S1b) - 0.5f * (S2a + S2b);

    // ---- CTA reduce + one atomic; last CTA writes the final output ----
    #pragma unroll
    for (int o = 16; o > 0; o >>= 1)
        acc += __shfl_xor_sync(0xFFFFFFFFu, acc, o);
    if (lane == 0) shred[wid] = acc;
    __syncthreads();
    if (tid == 0) {
        float s = 0.f;
        #pragma unroll
        for (int i = 0; i < NWARPS; i++) s += shred[i];
        atomicAdd(&g_acc, s);
        __threadfence();
        unsigned d = atomicAdd(&g_done, 1u);
        if ((d % NC) == NC - 1u) {
            float total = atomicAdd(&g_acc, 0.0f);
            out[0] = total * (1.0f / (float)BATCH);   // loss = +g_acc/B
        }
    }
}

// ---------------------------------------------------------------------------
extern "C" void kernel_launch(void* const* d_in, const int* in_sizes, int n_in,
                              void* d_out, int out_size)
{
    const float* loc = (const float*)d_in[0];
    const float* che = (const float*)d_in[1];
    const float* tp  = (const float*)d_in[2];
    const float* bb  = (const float*)d_in[3];
    float* out = (float*)d_out;

    static int ncta = 0;
    if (ncta == 0) {
        int nsm = 0;
        cudaDeviceGetAttribute(&nsm, cudaDevAttrMultiProcessorCount, 0);
        if (nsm <= 0) nsm = 148;
        ncta = 2 * nsm;                    // 2 CTAs/SM, all resident
        cudaFuncSetAttribute(fused_loss_kernel,
                             cudaFuncAttributeMaxDynamicSharedMemorySize, SMEM_TOTAL);
    }
    fused_loss_kernel<<<ncta, 256, SMEM_TOTAL>>>(loc, che, tp, bb, out);
}

// round 15
// speedup vs baseline: 1.0715x; 1.0715x over previous
#include <cuda_runtime.h>
#include <cuda_fp16.h>
#include <cstdint>

// ---------------------------------------------------------------------------
// B=8192, D=256.
// loss = -sum_ij log_sigmoid(y_ij * (che_i . loc_j * exp(t') + b)) / B
// y = +1 diag, -1 off-diag.
//
// R15: 3 CTAs/SM (fp16-accum MMA makes the registers fit): tile 128x128,
//      8 warps of 64x32 (32 accum regs), ring-2 of K=64 chunks (32KB each,
//      64KB/CTA), f32 S1/S2 epilogue (R13's — the f16x2 variant of R14
//      regressed). Three independent convoy streams per SM raise tensor
//      duty; 6 warps/SMSP hide LDSM/MMA latency.
// ---------------------------------------------------------------------------

#define BATCH  8192
#define DIM    256
#define TM     128
#define TN     128
#define NTILES ((BATCH / TM) * (BATCH / TN))   // 4096
#define NWARPS 8

#define CHUNK_BYTES (256 * 128)                // (128 A + 128 B) rows x 128B
#define SMEM_TOTAL  (2 * CHUNK_BYTES)          // 65536

// Scratch (device globals; no allocation allowed): fp16 matrices
__device__ __half g_che[BATCH * DIM];
__device__ __half g_loc[BATCH * DIM];
__device__ float g_acc;
__device__ unsigned g_tile_ctr;
__device__ unsigned g_bar;      // monotonic barrier counter (epoch trick)
__device__ unsigned g_done;     // monotonic completion counter

__device__ __forceinline__ uint32_t smem_u32(const void* p) {
    uint32_t a;
    asm("{ .reg .u64 t; cvta.to.shared.u64 t, %1; cvt.u32.u64 %0, t; }"
        : "=r"(a) : "l"(p));
    return a;
}

__device__ __forceinline__ float ex2_approx(float x) {
    float y;
    asm("ex2.approx.ftz.f32 %0, %1;" : "=f"(y) : "f"(x));
    return y;
}

__device__ __forceinline__ void ldmatrix_x4(uint32_t* r, uint32_t addr) {
    asm volatile("ldmatrix.sync.aligned.m8n8.x4.shared.b16 {%0,%1,%2,%3}, [%4];"
                 : "=r"(r[0]), "=r"(r[1]), "=r"(r[2]), "=r"(r[3])
                 : "r"(addr));
}

// fp16-accumulator MMA: D(16x8,f16) += A(16x16,f16) x B(16x8,f16)
__device__ __forceinline__ void mma_f16acc(uint32_t* c, const uint32_t* a,
                                           uint32_t b0, uint32_t b1) {
    asm volatile(
        "mma.sync.aligned.m16n8k16.row.col.f16.f16.f16.f16 "
        "{%0,%1}, {%2,%3,%4,%5}, {%6,%7}, {%0,%1};"
        : "+r"(c[0]), "+r"(c[1])
        : "r"(a[0]), "r"(a[1]), "r"(a[2]), "r"(a[3]), "r"(b0), "r"(b1));
}

#define CP_ASYNC16(dst, src) \
    asm volatile("cp.async.cg.shared.global [%0], [%1], 16;" \
                 :: "r"(dst), "l"(src) : "memory")
#define CP_COMMIT() asm volatile("cp.async.commit_group;" ::: "memory")
#define CP_WAIT(n)  asm volatile("cp.async.wait_group %0;" :: "n"(n) : "memory")

// ---------------------------------------------------------------------------
// Prefetch one K=64 chunk (128 A rows + 128 B rows, 128B each) into a
// swizzled ring slot. 256 threads x 8 cp.async of 16B.
// ---------------------------------------------------------------------------
__device__ __forceinline__ void prefetch_chunk(uint32_t dstBase, int m0, int n0,
                                               int chunk, int tid)
{
    int r0 = tid >> 3;                       // 0..31
    int cc = tid & 7;                        // 16B slot in 128B row
    uint32_t swx = ((uint32_t)(cc << 4)) ^ ((uint32_t)((r0 & 7) << 4));
    const __half* srcA = g_che + (size_t)(m0 + r0) * DIM + chunk * 64 + cc * 8;
    const __half* srcB = g_loc + (size_t)(n0 + r0) * DIM + chunk * 64 + cc * 8;
    #pragma unroll
    for (int it = 0; it < 4; it++) {
        uint32_t dst = dstBase + (uint32_t)((r0 + it * 32) << 7) + swx;
        CP_ASYNC16(dst, srcA + (size_t)(it * 32) * DIM);
    }
    #pragma unroll
    for (int it = 0; it < 4; it++) {
        uint32_t dst = dstBase + (uint32_t)((r0 + it * 32 + TM) << 7) + swx;
        CP_ASYNC16(dst, srcB + (size_t)(it * 32) * DIM);
    }
}

// ---------------------------------------------------------------------------
// Compute one K=64 chunk: 4 k16 steps over this warp's 64x32 fragment.
// Per ks: A m64k16 = 4 ldmatrix.x4, B n32k16 = 2 ldmatrix.x4, 16 MMAs.
// ---------------------------------------------------------------------------
__device__ __forceinline__ void compute_chunk(uint32_t base,
                                              const uint32_t* aRB, const uint32_t* aX,
                                              const uint32_t* bRB, const uint32_t* bX,
                                              uint32_t kloA, uint32_t kloB,
                                              uint32_t (*c)[2])
{
    #pragma unroll
    for (int ks = 0; ks < 4; ks++) {
        uint32_t koff = (uint32_t)(ks << 5);   // 32B per k16 step
        uint32_t a[4][4], b[2][4];
        #pragma unroll
        for (int i = 0; i < 4; i++)
            ldmatrix_x4(a[i], base + aRB[i] + ((koff + kloA) ^ aX[i]));
        #pragma unroll
        for (int q = 0; q < 2; q++)
            ldmatrix_x4(b[q], base + bRB[q] + ((koff + kloB) ^ bX[q]));
        #pragma unroll
        for (int mt = 0; mt < 4; mt++) {
            #pragma unroll
            for (int nt = 0; nt < 4; nt++) {
                uint32_t b0 = b[nt >> 1][(nt & 1) ? 2 : 0];
                uint32_t b1 = b[nt >> 1][(nt & 1) ? 3 : 1];
                mma_f16acc(c[mt * 4 + nt], a[mt], b0, b1);
            }
        }
    }
}

// ---------------------------------------------------------------------------
// Fused kernel: norm -> device barrier -> persistent GEMM+loss -> output.
// ---------------------------------------------------------------------------
__global__ __launch_bounds__(256, 3)
void fused_loss_kernel(const float* __restrict__ loc,
                       const float* __restrict__ che,
                       const float* __restrict__ t_prime,
                       const float* __restrict__ b_in,
                       float* __restrict__ out)
{
    extern __shared__ __align__(128) char smem[];
    const uint32_t sBase = smem_u32(smem);
    const unsigned NC = gridDim.x;

    __shared__ unsigned sh_next;
    __shared__ float shred[NWARPS];

    int tid = threadIdx.x;
    int wid = tid >> 5;
    int lane = tid & 31;

    // ================= Phase 1: row L2-normalize -> fp16 ====================
    {
        int gwarp = blockIdx.x * NWARPS + wid;
        for (int row = gwarp; row < BATCH; row += (int)NC * NWARPS) {
            const float4* l4 = reinterpret_cast<const float4*>(loc + row * DIM) + lane * 2;
            const float4* c4 = reinterpret_cast<const float4*>(che + row * DIM) + lane * 2;
            float4 a0 = l4[0], a1 = l4[1];
            float4 b0 = c4[0], b1 = c4[1];

            float s0 = a0.x*a0.x + a0.y*a0.y + a0.z*a0.z + a0.w*a0.w
                     + a1.x*a1.x + a1.y*a1.y + a1.z*a1.z + a1.w*a1.w;
            float s1 = b0.x*b0.x + b0.y*b0.y + b0.z*b0.z + b0.w*b0.w
                     + b1.x*b1.x + b1.y*b1.y + b1.z*b1.z + b1.w*b1.w;
            #pragma unroll
            for (int o = 16; o > 0; o >>= 1) {
                s0 += __shfl_xor_sync(0xFFFFFFFFu, s0, o);
                s1 += __shfl_xor_sync(0xFFFFFFFFu, s1, o);
            }
            float r0 = rsqrtf(s0);
            float r1 = rsqrtf(s1);

            __half2 h[4];
            h[0] = __float22half2_rn(make_float2(a0.x*r0, a0.y*r0));
            h[1] = __float22half2_rn(make_float2(a0.z*r0, a0.w*r0));
            h[2] = __float22half2_rn(make_float2(a1.x*r0, a1.y*r0));
            h[3] = __float22half2_rn(make_float2(a1.z*r0, a1.w*r0));
            *reinterpret_cast<uint4*>(g_loc + row * DIM + lane * 8) =
                *reinterpret_cast<uint4*>(h);

            h[0] = __float22half2_rn(make_float2(b0.x*r1, b0.y*r1));
            h[1] = __float22half2_rn(make_float2(b0.z*r1, b0.w*r1));
            h[2] = __float22half2_rn(make_float2(b1.x*r1, b1.y*r1));
            h[3] = __float22half2_rn(make_float2(b1.z*r1, b1.w*r1));
            *reinterpret_cast<uint4*>(g_che + row * DIM + lane * 8) =
                *reinterpret_cast<uint4*>(h);
        }
    }

    float scale = expf(t_prime[0]);
    float shift = b_in[0];

    if (blockIdx.x == 0 && tid == 0) {
        atomicExch(&g_tile_ctr, 0u);
        atomicExch(&g_acc, 0.0f);
    }
    __threadfence();
    __syncthreads();

    // ============ device-wide epoch spin barrier (all CTAs resident) =======
    if (tid == 0) {
        unsigned t = atomicAdd(&g_bar, 1u);
        unsigned target = (t / NC + 1u) * NC;
        while (atomicAdd(&g_bar, 0u) < target) { }
    }
    __threadfence();
    __syncthreads();

    // ================= Phase 2: persistent GEMM + loss ======================
    int am = (wid & 1) * 64;
    int bn = (wid >> 1) * 32;

    uint32_t aRB[4], aX[4], bRB[2], bX[2];
    #pragma unroll
    for (int i = 0; i < 4; i++) {
        int r = am + i * 16 + (lane & 15);
        aRB[i] = (uint32_t)(r << 7);
        aX[i]  = (uint32_t)((r & 7) << 4);
    }
    #pragma unroll
    for (int q = 0; q < 2; q++) {
        int r = TM + bn + q * 16 + ((lane >> 4) << 3) + (lane & 7);
        bRB[q] = (uint32_t)(r << 7);
        bX[q]  = (uint32_t)((r & 7) << 4);
    }
    uint32_t kloA = (uint32_t)((lane >> 4) << 4);
    uint32_t kloB = (uint32_t)(((lane >> 3) & 1) << 4);

    uint32_t c[16][2];
    #pragma unroll
    for (int i = 0; i < 16; i++) { c[i][0] = 0u; c[i][1] = 0u; }

    float acc = 0.0f;                 // exact diagonal-tile contributions
    float S1a = 0.f, S1b = 0.f;       // running sum(e)    (off-diag tiles)
    float S2a = 0.f, S2b = 0.f;       // running sum(e^2)
    const float LOG2E = 1.4426950408889634f;
    float k1 = scale * LOG2E;
    float k0 = shift * LOG2E;

    if (tid == 0) sh_next = atomicAdd(&g_tile_ctr, 1u);
    __syncthreads();
    unsigned cur = sh_next;

    int m0 = (int)(cur & 63) * TM;
    int n0 = (int)(cur >> 6) * TN;

    // warm: chunk 0 of first tile into slot 0
    prefetch_chunk(sBase, m0, n0, 0, tid);
    CP_COMMIT();

    int sc = 0;                       // ring slot of the chunk being computed
    unsigned nxt = 0;
    for (;;) {
        int nm0 = 0, nn0 = 0;

        #pragma unroll
        for (int k = 0; k < 4; k++) {
            __syncthreads();       // all warps done with slot sc^1's old data

            if (k == 0) {
                if (tid == 0) sh_next = atomicAdd(&g_tile_ctr, 1u);
            } else if (k == 1) {
                nxt = sh_next;                // written k=0, barrier at k=1
                nm0 = (int)(nxt & 63) * TM;
                nn0 = (int)(nxt >> 6) * TN;
            }

            // prefetch the NEXT stream chunk into the other slot
            uint32_t pslot = sBase + (uint32_t)((sc ^ 1) * CHUNK_BYTES);
            if (k < 3)             prefetch_chunk(pslot, m0, n0, k + 1, tid);
            else if (nxt < NTILES) prefetch_chunk(pslot, nm0, nn0, 0, tid);
            CP_COMMIT();

            CP_WAIT(1);            // current chunk's group complete
            compute_chunk(sBase + (uint32_t)(sc * CHUNK_BYTES),
                          aRB, aX, bRB, bX, kloA, kloB, c);
            sc ^= 1;
        }

        // ---- epilogue for tile cur (next tile's chunk-0 load streams) ----
        if (m0 != n0) {
            // no diagonal element: sum log1p(e) ~ S1 - S2/2, applied at end
            #pragma unroll
            for (int i = 0; i < 16; i++) {
                float2 f0 = __half22float2(*reinterpret_cast<__half2*>(&c[i][0]));
                float2 f1 = __half22float2(*reinterpret_cast<__half2*>(&c[i][1]));
                float e0 = ex2_approx(fmaf(f0.x, k1, k0));
                float e1 = ex2_approx(fmaf(f0.y, k1, k0));
                float e2 = ex2_approx(fmaf(f1.x, k1, k0));
                float e3 = ex2_approx(fmaf(f1.y, k1, k0));
                S1a += e0; S2a = fmaf(e0, e0, S2a);
                S1b += e1; S2b = fmaf(e1, e1, S2b);
                S1a += e2; S2a = fmaf(e2, e2, S2a);
                S1b += e3; S2b = fmaf(e3, e3, S2b);
                c[i][0] = 0u; c[i][1] = 0u;
            }
        } else {
            // diagonal tile: exact per-element handling (64 of 4096 tiles)
            int rbase = m0 + am + (lane >> 2);
            int cbase = n0 + bn + (lane & 3) * 2;
            #pragma unroll
            for (int mt = 0; mt < 4; mt++) {
                #pragma unroll
                for (int nt = 0; nt < 4; nt++) {
                    uint32_t* cc = c[mt * 4 + nt];
                    int col0 = cbase + nt * 8;
                    #pragma unroll
                    for (int j = 0; j < 2; j++) {
                        float2 f = __half22float2(*reinterpret_cast<__half2*>(&cc[j]));
                        int row = rbase + mt * 16 + j * 8;
                        #pragma unroll
                        for (int u = 0; u < 2; u++) {
                            float d = (u == 0) ? f.x : f.y;
                            int col = col0 + u;
                            float z = fmaf(d, scale, shift);
                            float v = (row == col) ? z : -z;   // y*z
                            float av = fabsf(v);
                            float e = __expf(-av);
                            float l;
                            if (e < 0.0625f) {
                                l = e * fmaf(e, fmaf(e, 0.33333333f, -0.5f), 1.0f);
                            } else {
                                l = log1pf(e);                 // near-diagonal only
                            }
                            acc += fmaxf(-v, 0.0f) + l;        // softplus(-v)
                        }
                        cc[j] = 0u;
                    }
                }
            }
        }

        if (nxt >= NTILES) break;
        cur = nxt; m0 = nm0; n0 = nn0;
    }

    // fold running sums: sum log1p(e) ~ S1 - S2/2
    acc += (S1a + S1b) - 0.5f * (S2a + S2b);

    // ---- CTA reduce + one atomic; last CTA writes the final output ----
    #pragma unroll
    for (int o = 16; o > 0; o >>= 1)
        acc += __shfl_xor_sync(0xFFFFFFFFu, acc, o);
    if (lane == 0) shred[wid] = acc;
    __syncthreads();
    if (tid == 0) {
        float s = 0.f;
        #pragma unroll
        for (int i = 0; i < NWARPS; i++) s += shred[i];
        atomicAdd(&g_acc, s);
        __threadfence();
        unsigned d = atomicAdd(&g_done, 1u);
        if ((d % NC) == NC - 1u) {
            float total = atomicAdd(&g_acc, 0.0f);
            out[0] = total * (1.0f / (float)BATCH);   // loss = +g_acc/B
        }
    }
}

// ---------------------------------------------------------------------------
extern "C" void kernel_launch(void* const* d_in, const int* in_sizes, int n_in,
                              void* d_out, int out_size)
{
    const float* loc = (const float*)d_in[0];
    const float* che = (const float*)d_in[1];
    const float* tp  = (const float*)d_in[2];
    const float* bb  = (const float*)d_in[3];
    float* out = (float*)d_out;

    static int ncta = 0;
    if (ncta == 0) {
        int nsm = 0;
        cudaDeviceGetAttribute(&nsm, cudaDevAttrMultiProcessorCount, 0);
        if (nsm <= 0) nsm = 148;
        ncta = 3 * nsm;                    // 3 CTAs/SM, all resident
        cudaFuncSetAttribute(fused_loss_kernel,
                             cudaFuncAttributeMaxDynamicSharedMemorySize, SMEM_TOTAL);
    }
    fused_loss_kernel<<<ncta, 256, SMEM_TOTAL>>>(loc, che, tp, bb, out);
}